// round 1
// baseline (speedup 1.0000x reference)
#include <cuda_runtime.h>

#define FULL 0xffffffffu

// Precomputed (cos(t/2), sin(t/2)) for all launch-constant gate params.
__device__ float2 g_trig[124];

// offsets into g_trig
#define Q_ROT 0
#define Q_CRX 24
#define K_ROT 32
#define K_CRX 56
#define V_ROT 64
#define V_CRX 88
#define C_ROT 96
#define C_CRX 108
#define C_CRX2 116

__global__ void trig_setup(const float* qr, const float* qc, const float* kr, const float* kc,
                           const float* vr, const float* vc, const float* cr, const float* cc,
                           const float* cc2) {
    int t = threadIdx.x;
    float p = 0.f;
    if (t < 24) p = qr[t];
    else if (t < 32) p = qc[t - 24];
    else if (t < 56) p = kr[t - 32];
    else if (t < 64) p = kc[t - 56];
    else if (t < 88) p = vr[t - 64];
    else if (t < 96) p = vc[t - 88];
    else if (t < 108) p = cr[t - 96];
    else if (t < 116) p = cc[t - 108];
    else if (t < 124) p = cc2[t - 116];
    if (t < 124) {
        float s, c;
        sincosf(0.5f * p, &s, &c);
        g_trig[t] = make_float2(c, s);
    }
}

// ---------------------------------------------------------------------------
// 8-qubit state: global amp index i = (lane << 3) | j.  Wire w -> bit w.
// Wires 0..2 are local bits (j), wires 3..7 are lane bits.
// ---------------------------------------------------------------------------

__device__ __forceinline__ float wredsum(float v) {
#pragma unroll
    for (int o = 16; o; o >>= 1) v += __shfl_xor_sync(FULL, v, o);
    return v;
}

__device__ __forceinline__ int bit8(int lane, int j, int w) {
    return (w < 3) ? ((j >> w) & 1) : ((lane >> (w - 3)) & 1);
}

// o[j] = amplitude at global index (i ^ m)
__device__ __forceinline__ void gather8(const float2* a, float2* o, int m) {
    const int mloc = m & 7, mlane = m >> 3;
#pragma unroll
    for (int j = 0; j < 8; j++) {
        float2 t = a[j ^ mloc];
        if (mlane) {
            t.x = __shfl_xor_sync(FULL, t.x, mlane);
            t.y = __shfl_xor_sync(FULL, t.y, mlane);
        }
        o[j] = t;
    }
}

// RZ: diag(e, conj(e)), e = cos(t/2) - i sin(t/2)
__device__ __forceinline__ void gRZ(float2* a, int lane, int w, float c, float s) {
#pragma unroll
    for (int j = 0; j < 8; j++) {
        float ei = bit8(lane, j, w) ? s : -s;
        float2 x = a[j];
        a[j] = make_float2(x.x * c - x.y * ei, x.x * ei + x.y * c);
    }
}

// combine: new = c*a + (-i s)*o
__device__ __forceinline__ float2 rxmix(float2 a, float2 o, float c, float s) {
    return make_float2(c * a.x + s * o.y, c * a.y - s * o.x);
}

__device__ __forceinline__ void gRX(float2* a, int lane, int w, float c, float s) {
    float2 o[8];
    gather8(a, o, 1 << w);
#pragma unroll
    for (int j = 0; j < 8; j++) a[j] = rxmix(a[j], o[j], c, s);
}

__device__ __forceinline__ void gCRX(float2* a, int lane, int wc, int wt, float c, float s) {
    float2 o[8];
    gather8(a, o, 1 << wt);
#pragma unroll
    for (int j = 0; j < 8; j++)
        if (bit8(lane, j, wc)) a[j] = rxmix(a[j], o[j], c, s);
}

// IsingXX: c*I + (-i s)*X(w1)X(w2) -> partner flips both bits
__device__ __forceinline__ void gIXX(float2* a, int lane, int w1, int w2, float c, float s) {
    float2 o[8];
    gather8(a, o, (1 << w1) | (1 << w2));
#pragma unroll
    for (int j = 0; j < 8; j++) a[j] = rxmix(a[j], o[j], c, s);
}

__device__ __forceinline__ void gCNOT(float2* a, int lane, int wc, int wt) {
    float2 o[8];
    gather8(a, o, 1 << wt);
#pragma unroll
    for (int j = 0; j < 8; j++)
        if (bit8(lane, j, wc)) a[j] = o[j];
}

template <int OFF>
__device__ __forceinline__ void rot_layer8(float2* a, int lane, const float2* t) {
#pragma unroll
    for (int i = 0; i < 4; i++) {
        float2 t0 = t[3 * i], t1 = t[3 * i + 1], t2 = t[3 * i + 2];
        gRZ(a, lane, OFF + i, t0.x, t0.y);
        gRX(a, lane, OFF + i, t1.x, t1.y);
        gRZ(a, lane, OFF + i, t2.x, t2.y);
    }
}

template <int OFF>
__device__ __forceinline__ void two_ring8(float2* a, int lane, const float2* rot, const float2* crx) {
    rot_layer8<OFF>(a, lane, rot);
#pragma unroll
    for (int i = 0; i < 4; i++) {
        float2 t = crx[i];
        gCRX(a, lane, OFF + i, OFF + ((i + 1) & 3), t.x, t.y);
    }
#pragma unroll
    for (int i = 0; i < 4; i++) {
        float2 t = crx[4 + i];
        gIXX(a, lane, OFF + i, OFF + ((i + 1) & 3), t.x, t.y);
    }
    rot_layer8<OFF>(a, lane, rot + 12);
}

// ---------------------------------------------------------------------------
// 4-qubit value circuit: 16 amps in per-thread registers (redundant per lane).
// ---------------------------------------------------------------------------

__device__ __forceinline__ void pairRX(float2& a0, float2& a1, float c, float s) {
    float2 n0 = make_float2(c * a0.x + s * a1.y, c * a0.y - s * a1.x);
    float2 n1 = make_float2(c * a1.x + s * a0.y, c * a1.y - s * a0.x);
    a0 = n0;
    a1 = n1;
}

__device__ __forceinline__ void vRZ(float2* v, int w, float c, float s) {
#pragma unroll
    for (int i = 0; i < 16; i++) {
        float ei = ((i >> w) & 1) ? s : -s;
        float2 x = v[i];
        v[i] = make_float2(x.x * c - x.y * ei, x.x * ei + x.y * c);
    }
}

__device__ __forceinline__ void vRX(float2* v, int w, float c, float s) {
#pragma unroll
    for (int i = 0; i < 16; i++)
        if (!((i >> w) & 1)) pairRX(v[i], v[i | (1 << w)], c, s);
}

__device__ __forceinline__ void vCRX(float2* v, int wc, int wt, float c, float s) {
#pragma unroll
    for (int i = 0; i < 16; i++)
        if (((i >> wc) & 1) && !((i >> wt) & 1)) pairRX(v[i], v[i | (1 << wt)], c, s);
}

__device__ __forceinline__ void vIXX(float2* v, int w1, int w2, float c, float s) {
    const int m = (1 << w1) | (1 << w2);
#pragma unroll
    for (int i = 0; i < 16; i++)
        if (!((i >> w1) & 1)) pairRX(v[i], v[i ^ m], c, s);
}

__device__ __forceinline__ void vCNOT(float2* v, int wc, int wt) {
#pragma unroll
    for (int i = 0; i < 16; i++)
        if (((i >> wc) & 1) && !((i >> wt) & 1)) {
            float2 tmp = v[i];
            v[i] = v[i | (1 << wt)];
            v[i | (1 << wt)] = tmp;
        }
}

__device__ __forceinline__ void vrot(float2* v, const float2* t) {
#pragma unroll
    for (int i = 0; i < 4; i++) {
        float2 t0 = t[3 * i], t1 = t[3 * i + 1], t2 = t[3 * i + 2];
        vRZ(v, i, t0.x, t0.y);
        vRX(v, i, t1.x, t1.y);
        vRZ(v, i, t2.x, t2.y);
    }
}

// ---------------------------------------------------------------------------

__global__ void __launch_bounds__(256)
qa_kernel(const float* __restrict__ x_text, const float* __restrict__ x_image,
          const float* __restrict__ W_text, const float* __restrict__ b_text,
          const float* __restrict__ W_image, const float* __restrict__ b_image,
          const float* __restrict__ score_gates,
          float* __restrict__ out, int B, int IN) {
    int gw = (int)((blockIdx.x * blockDim.x + threadIdx.x) >> 5);
    int lane = threadIdx.x & 31;
    if (gw >= B) return;

    const float2* TR = g_trig;

    // ---- projections: xq = W_text @ x_text_row + b, xk likewise ----
    float xq[4], xk[4];
    {
        const float* xt = x_text + (long)gw * IN;
        const float* xi = x_image + (long)gw * IN;
#pragma unroll
        for (int r = 0; r < 4; r++) {
            float pq = 0.f, pk = 0.f;
            for (int k = lane; k < IN; k += 32) {
                pq += xt[k] * __ldg(&W_text[r * IN + k]);
                pk += xi[k] * __ldg(&W_image[r * IN + k]);
            }
            xq[r] = wredsum(pq) + __ldg(&b_text[r]);
            xk[r] = wredsum(pk) + __ldg(&b_image[r]);
        }
    }

    // ---- score circuit: 8 qubits ----
    float2 a[8];
#pragma unroll
    for (int j = 0; j < 8; j++) a[j] = make_float2(0.f, 0.f);
    a[0].x = (lane == 0) ? 1.f : 0.f;

#pragma unroll
    for (int i = 0; i < 4; i++) {
        float s, c;
        __sincosf(0.5f * xq[i], &s, &c);
        gRX(a, lane, i, c, s);
    }
    two_ring8<0>(a, lane, TR + Q_ROT, TR + Q_CRX);
#pragma unroll
    for (int i = 0; i < 4; i++) {
        float s, c;
        __sincosf(0.5f * xk[i], &s, &c);
        gRX(a, lane, 4 + i, c, s);
    }
    two_ring8<4>(a, lane, TR + K_ROT, TR + K_CRX);

    // cross CRX pairs
#pragma unroll
    for (int i = 0; i < 4; i++) {
        float2 t = TR[C_CRX + i];
        gCRX(a, lane, i, 4 + i, t.x, t.y);
        float2 u = TR[C_CRX + 4 + i];
        gCRX(a, lane, 4 + i, i, u.x, u.y);
    }
#pragma unroll
    for (int i = 0; i < 4; i++) {
        float2 t = TR[C_CRX2 + i];
        gCRX(a, lane, i, ((i + 1) & 3) + 4, t.x, t.y);
    }
#pragma unroll
    for (int i = 0; i < 4; i++) {
        float2 t = TR[C_CRX2 + 4 + i];
        gCRX(a, lane, 4 + i, (i + 1) & 3, t.x, t.y);
    }
#pragma unroll
    for (int i = 0; i < 4; i++) {
        gCNOT(a, lane, i, 4 + i);
        gCNOT(a, lane, 4 + i, i);
    }
    rot_layer8<0>(a, lane, TR + C_ROT);

    // measurements -> amp
    float amp4[4];
#pragma unroll
    for (int w = 0; w < 4; w++) {
        float2 o[8];
        gather8(a, o, 1 << w);
        float z = 0.f, x = 0.f;
#pragma unroll
        for (int j = 0; j < 8; j++) {
            float n = a[j].x * a[j].x + a[j].y * a[j].y;
            z += bit8(lane, j, w) ? -n : n;
            x += a[j].x * o[j].x + a[j].y * o[j].y;
        }
        z = wredsum(z);
        x = wredsum(x);
        amp4[w] = sqrtf(z * z + x * x);
    }

    // ---- value circuit: 4 qubits ----
    float2 v[16];
#pragma unroll
    for (int i = 0; i < 16; i++) v[i] = make_float2(0.f, 0.f);
    v[0].x = 1.f;

#pragma unroll
    for (int i = 0; i < 4; i++) {
        float s, c;
        __sincosf(0.5f * xk[i], &s, &c);
        vRX(v, i, c, s);
    }
    vrot(v, TR + V_ROT);
#pragma unroll
    for (int i = 0; i < 4; i++) {
        float2 t = TR[V_CRX + i];
        vCRX(v, i, (i + 1) & 3, t.x, t.y);
    }
#pragma unroll
    for (int i = 0; i < 4; i++) {
        float2 t = TR[V_CRX + 4 + i];
        vIXX(v, i, (i + 1) & 3, t.x, t.y);
    }
    vrot(v, TR + V_ROT + 12);
#pragma unroll
    for (int i = 0; i < 4; i++) {
        float ang = tanhf(amp4[i]) * __ldg(&score_gates[i]);
        float s, c;
        __sincosf(0.5f * ang, &s, &c);
        vRX(v, i, c, s);
    }
#pragma unroll
    for (int i = 0; i < 4; i++) vCNOT(v, i, (i + 1) & 3);

    // measure + write (all lanes hold identical v; lane 0 stores)
    float zres[4], xres[4];
#pragma unroll
    for (int w = 0; w < 4; w++) {
        float z = 0.f, x = 0.f;
#pragma unroll
        for (int i = 0; i < 16; i++) {
            float n = v[i].x * v[i].x + v[i].y * v[i].y;
            z += ((i >> w) & 1) ? -n : n;
            x += v[i].x * v[i ^ (1 << w)].x + v[i].y * v[i ^ (1 << w)].y;
        }
        zres[w] = z;
        xres[w] = x;
    }
    if (lane == 0) {
        float4* o0 = (float4*)(out + (long)gw * 8);
        o0[0] = make_float4(zres[0], zres[1], zres[2], zres[3]);
        o0[1] = make_float4(xres[0], xres[1], xres[2], xres[3]);
    }
}

extern "C" void kernel_launch(void* const* d_in, const int* in_sizes, int n_in,
                              void* d_out, int out_size) {
    const float* x_text  = (const float*)d_in[0];
    const float* x_image = (const float*)d_in[1];
    const float* W_text  = (const float*)d_in[2];
    const float* b_text  = (const float*)d_in[3];
    const float* W_image = (const float*)d_in[4];
    const float* b_image = (const float*)d_in[5];
    const float* q_rot   = (const float*)d_in[6];
    const float* q_crx   = (const float*)d_in[7];
    const float* k_rot   = (const float*)d_in[8];
    const float* k_crx   = (const float*)d_in[9];
    const float* v_rot   = (const float*)d_in[10];
    const float* v_crx   = (const float*)d_in[11];
    const float* c_rot   = (const float*)d_in[12];
    const float* c_crx   = (const float*)d_in[13];
    const float* c_crx2  = (const float*)d_in[14];
    const float* gates   = (const float*)d_in[15];

    int IN = in_sizes[2] / 4;        // W_text is [4, IN]
    int B  = in_sizes[0] / IN;       // x_text is [B, IN]

    trig_setup<<<1, 128>>>(q_rot, q_crx, k_rot, k_crx, v_rot, v_crx, c_rot, c_crx, c_crx2);

    int threads = 256;
    int blocks = (B * 32 + threads - 1) / threads;
    qa_kernel<<<blocks, threads>>>(x_text, x_image, W_text, b_text, W_image, b_image,
                                   gates, (float*)d_out, B, IN);
}

// round 2
// speedup vs baseline: 1.2445x; 1.2445x over previous
#include <cuda_runtime.h>

#define FULL 0xffffffffu

// ---------------------------------------------------------------------------
// Precomputed constant-gate tables (filled by setup kernel).
// g_fused: fused RZ*RX*RZ triples as (u00.x, u00.y, u01.x, u01.y)
//   [0..3]  q ring layer1 wires 0..3     [4..7]  q ring layer2
//   [8..11] k ring layer1               [12..15] k ring layer2
//   [16..19] cross final layer          [20..23] v ring layer1
//   [24..27] v ring layer2
// g_cs: (cos(t/2), sin(t/2))
//   [0..7] q_crx, [8..15] k_crx, [16..23] c_crx, [24..31] c_crx2, [32..39] v_crx
// ---------------------------------------------------------------------------
__device__ float4 g_fused[28];
__device__ float2 g_cs[40];

// scratch between kernel A and B (B up to 16384)
__device__ float g_xk[16384 * 4];
__device__ float g_amp[16384 * 4];

__global__ void setup_kernel(const float* qr, const float* qc, const float* kr,
                             const float* kc, const float* vr, const float* vc,
                             const float* cr, const float* cc, const float* cc2) {
    int t = threadIdx.x;
    if (t < 28) {
        int grp = t >> 2, i = t & 3;
        float a = 0.f, b = 0.f, c = 0.f;
        switch (grp) {
            case 0: a = qr[3 * i];      b = qr[3 * i + 1];      c = qr[3 * i + 2];      break;
            case 1: a = qr[12 + 3 * i]; b = qr[12 + 3 * i + 1]; c = qr[12 + 3 * i + 2]; break;
            case 2: a = kr[3 * i];      b = kr[3 * i + 1];      c = kr[3 * i + 2];      break;
            case 3: a = kr[12 + 3 * i]; b = kr[12 + 3 * i + 1]; c = kr[12 + 3 * i + 2]; break;
            case 4: a = cr[3 * i];      b = cr[3 * i + 1];      c = cr[3 * i + 2];      break;
            case 5: a = vr[3 * i];      b = vr[3 * i + 1];      c = vr[3 * i + 2];      break;
            case 6: a = vr[12 + 3 * i]; b = vr[12 + 3 * i + 1]; c = vr[12 + 3 * i + 2]; break;
        }
        float cb = cosf(0.5f * b), sb = sinf(0.5f * b);
        float sum = 0.5f * (a + c), dif = 0.5f * (a - c);
        // u00 = cb * e^{-i sum}, u01 = sb*sin(dif) - i sb*cos(dif)
        g_fused[t] = make_float4(cb * cosf(sum), -cb * sinf(sum),
                                 sb * sinf(dif), -sb * cosf(dif));
    } else if (t < 68) {
        int u = t - 28;
        float v;
        if (u < 8) v = qc[u];
        else if (u < 16) v = kc[u - 8];
        else if (u < 24) v = cc[u - 16];
        else if (u < 32) v = cc2[u - 24];
        else v = vc[u - 32];
        float s, c;
        sincosf(0.5f * v, &s, &c);
        g_cs[u] = make_float2(c, s);
    }
}

// ---------------------------------------------------------------------------
// Kernel A: score circuit, warp-per-item.
// 8-qubit state: amp index i = (lane << 3) | j. Wire w -> bit w.
// Wires 0..2 local bits, wires 3..7 lane bits.
// ---------------------------------------------------------------------------

__device__ __forceinline__ float wredsum(float v) {
#pragma unroll
    for (int o = 16; o; o >>= 1) v += __shfl_xor_sync(FULL, v, o);
    return v;
}

__device__ __forceinline__ int bit8(int lane, int j, int w) {
    return (w < 3) ? ((j >> w) & 1) : ((lane >> (w - 3)) & 1);
}

__device__ __forceinline__ void gather8(const float2* a, float2* o, int m) {
    const int mloc = m & 7, mlane = m >> 3;
#pragma unroll
    for (int j = 0; j < 8; j++) {
        float2 t = a[j ^ mloc];
        if (mlane) {
            t.x = __shfl_xor_sync(FULL, t.x, mlane);
            t.y = __shfl_xor_sync(FULL, t.y, mlane);
        }
        o[j] = t;
    }
}

// RZ: diag(e, conj(e)), e = cos - i sin
__device__ __forceinline__ void gRZ(float2* a, int lane, int w, float c, float s) {
#pragma unroll
    for (int j = 0; j < 8; j++) {
        float ei = bit8(lane, j, w) ? s : -s;
        float2 x = a[j];
        a[j] = make_float2(x.x * c - x.y * ei, x.x * ei + x.y * c);
    }
}

__device__ __forceinline__ float2 rxmix(float2 a, float2 o, float c, float s) {
    return make_float2(c * a.x + s * o.y, c * a.y - s * o.x);
}

__device__ __forceinline__ void gRX(float2* a, int lane, int w, float c, float s) {
    float2 o[8];
    gather8(a, o, 1 << w);
#pragma unroll
    for (int j = 0; j < 8; j++) a[j] = rxmix(a[j], o[j], c, s);
}

// general fused 1-qubit gate: bit0: new = u00*a + u01*o; bit1: new = conj(u00)*a - conj(u01)*o
__device__ __forceinline__ void gGEN(float2* a, int lane, int w, float4 u) {
    float2 o[8];
    gather8(a, o, 1 << w);
#pragma unroll
    for (int j = 0; j < 8; j++) {
        int b = bit8(lane, j, w);
        float cx = u.x;
        float cy = b ? -u.y : u.y;
        float dx = b ? -u.z : u.z;
        float dy = u.w;
        float2 x = a[j], p = o[j];
        a[j] = make_float2(cx * x.x - cy * x.y + dx * p.x - dy * p.y,
                           cx * x.y + cy * x.x + dx * p.y + dy * p.x);
    }
}

__device__ __forceinline__ void gCRX(float2* a, int lane, int wc, int wt, float c, float s) {
    float2 o[8];
    gather8(a, o, 1 << wt);
#pragma unroll
    for (int j = 0; j < 8; j++)
        if (bit8(lane, j, wc)) a[j] = rxmix(a[j], o[j], c, s);
}

__device__ __forceinline__ void gIXX(float2* a, int lane, int w1, int w2, float c, float s) {
    float2 o[8];
    gather8(a, o, (1 << w1) | (1 << w2));
#pragma unroll
    for (int j = 0; j < 8; j++) a[j] = rxmix(a[j], o[j], c, s);
}

__device__ __forceinline__ void gCNOT(float2* a, int lane, int wc, int wt) {
    float2 o[8];
    gather8(a, o, 1 << wt);
#pragma unroll
    for (int j = 0; j < 8; j++)
        if (bit8(lane, j, wc)) a[j] = o[j];
}

template <int OFF, int FBASE, int CSBASE>
__device__ __forceinline__ void two_ring8(float2* a, int lane) {
#pragma unroll
    for (int i = 0; i < 4; i++) gGEN(a, lane, OFF + i, g_fused[FBASE + i]);
#pragma unroll
    for (int i = 0; i < 4; i++) {
        float2 t = g_cs[CSBASE + i];
        gCRX(a, lane, OFF + i, OFF + ((i + 1) & 3), t.x, t.y);
    }
#pragma unroll
    for (int i = 0; i < 4; i++) {
        float2 t = g_cs[CSBASE + 4 + i];
        gIXX(a, lane, OFF + i, OFF + ((i + 1) & 3), t.x, t.y);
    }
#pragma unroll
    for (int i = 0; i < 4; i++) gGEN(a, lane, OFF + i, g_fused[FBASE + 4 + i]);
}

__global__ void __launch_bounds__(256)
score_kernel(const float* __restrict__ x_text, const float* __restrict__ x_image,
             const float* __restrict__ W_text, const float* __restrict__ b_text,
             const float* __restrict__ W_image, const float* __restrict__ b_image,
             int B, int IN) {
    int gw = (int)((blockIdx.x * blockDim.x + threadIdx.x) >> 5);
    int lane = threadIdx.x & 31;
    if (gw >= B) return;

    // projections
    float xq[4], xk[4];
    {
        const float* xt = x_text + (long)gw * IN;
        const float* xi = x_image + (long)gw * IN;
#pragma unroll
        for (int r = 0; r < 4; r++) {
            float pq = 0.f, pk = 0.f;
            for (int k = lane; k < IN; k += 32) {
                pq += xt[k] * __ldg(&W_text[r * IN + k]);
                pk += xi[k] * __ldg(&W_image[r * IN + k]);
            }
            xq[r] = wredsum(pq) + __ldg(&b_text[r]);
            xk[r] = wredsum(pk) + __ldg(&b_image[r]);
        }
    }

    float2 a[8];
#pragma unroll
    for (int j = 0; j < 8; j++) a[j] = make_float2(0.f, 0.f);
    a[0].x = (lane == 0) ? 1.f : 0.f;

#pragma unroll
    for (int i = 0; i < 4; i++) {
        float s, c;
        __sincosf(0.5f * xq[i], &s, &c);
        gRX(a, lane, i, c, s);
    }
    two_ring8<0, 0, 0>(a, lane);
#pragma unroll
    for (int i = 0; i < 4; i++) {
        float s, c;
        __sincosf(0.5f * xk[i], &s, &c);
        gRX(a, lane, 4 + i, c, s);
    }
    two_ring8<4, 8, 8>(a, lane);

    // cross entanglers
#pragma unroll
    for (int i = 0; i < 4; i++) {
        float2 t = g_cs[16 + i];
        gCRX(a, lane, i, 4 + i, t.x, t.y);
        float2 u = g_cs[16 + 4 + i];
        gCRX(a, lane, 4 + i, i, u.x, u.y);
    }
#pragma unroll
    for (int i = 0; i < 4; i++) {
        float2 t = g_cs[24 + i];
        gCRX(a, lane, i, ((i + 1) & 3) + 4, t.x, t.y);
    }
#pragma unroll
    for (int i = 0; i < 4; i++) {
        float2 t = g_cs[24 + 4 + i];
        gCRX(a, lane, 4 + i, (i + 1) & 3, t.x, t.y);
    }
#pragma unroll
    for (int i = 0; i < 4; i++) {
        gCNOT(a, lane, i, 4 + i);
        gCNOT(a, lane, 4 + i, i);
    }
    // final fused rot layer (wires 0..3)
#pragma unroll
    for (int i = 0; i < 4; i++) gGEN(a, lane, i, g_fused[16 + i]);

    // measurements -> amp
#pragma unroll
    for (int w = 0; w < 4; w++) {
        float2 o[8];
        gather8(a, o, 1 << w);
        float z = 0.f, x = 0.f;
#pragma unroll
        for (int j = 0; j < 8; j++) {
            float n = a[j].x * a[j].x + a[j].y * a[j].y;
            z += bit8(lane, j, w) ? -n : n;
            x += a[j].x * o[j].x + a[j].y * o[j].y;
        }
        z = wredsum(z);
        x = wredsum(x);
        if (lane == 0) g_amp[gw * 4 + w] = sqrtf(z * z + x * x);
    }
    if (lane < 4) g_xk[gw * 4 + lane] = xk[lane];
}

// ---------------------------------------------------------------------------
// Kernel B: value circuit, thread-per-item (16 amps in registers).
// ---------------------------------------------------------------------------

__device__ __forceinline__ void pairRX(float2& a0, float2& a1, float c, float s) {
    float2 n0 = make_float2(c * a0.x + s * a1.y, c * a0.y - s * a1.x);
    float2 n1 = make_float2(c * a1.x + s * a0.y, c * a1.y - s * a0.x);
    a0 = n0;
    a1 = n1;
}

__device__ __forceinline__ void pairGEN(float2& a0, float2& a1, float4 u) {
    float2 n0 = make_float2(u.x * a0.x - u.y * a0.y + u.z * a1.x - u.w * a1.y,
                            u.x * a0.y + u.y * a0.x + u.z * a1.y + u.w * a1.x);
    float2 n1 = make_float2(u.x * a1.x + u.y * a1.y - u.z * a0.x - u.w * a0.y,
                            u.x * a1.y - u.y * a1.x - u.z * a0.y + u.w * a0.x);
    a0 = n0;
    a1 = n1;
}

__device__ __forceinline__ void vRX(float2* v, int w, float c, float s) {
#pragma unroll
    for (int i = 0; i < 16; i++)
        if (!((i >> w) & 1)) pairRX(v[i], v[i | (1 << w)], c, s);
}

__device__ __forceinline__ void vGEN(float2* v, int w, float4 u) {
#pragma unroll
    for (int i = 0; i < 16; i++)
        if (!((i >> w) & 1)) pairGEN(v[i], v[i | (1 << w)], u);
}

__device__ __forceinline__ void vCRX(float2* v, int wc, int wt, float c, float s) {
#pragma unroll
    for (int i = 0; i < 16; i++)
        if (((i >> wc) & 1) && !((i >> wt) & 1)) pairRX(v[i], v[i | (1 << wt)], c, s);
}

__device__ __forceinline__ void vIXX(float2* v, int w1, int w2, float c, float s) {
    const int m = (1 << w1) | (1 << w2);
#pragma unroll
    for (int i = 0; i < 16; i++)
        if (!((i >> w1) & 1)) pairRX(v[i], v[i ^ m], c, s);
}

__device__ __forceinline__ void vCNOT(float2* v, int wc, int wt) {
#pragma unroll
    for (int i = 0; i < 16; i++)
        if (((i >> wc) & 1) && !((i >> wt) & 1)) {
            float2 tmp = v[i];
            v[i] = v[i | (1 << wt)];
            v[i | (1 << wt)] = tmp;
        }
}

__global__ void __launch_bounds__(64)
value_kernel(const float* __restrict__ score_gates, float* __restrict__ out, int B) {
    int it = blockIdx.x * blockDim.x + threadIdx.x;
    if (it >= B) return;

    float xk[4], amp4[4];
#pragma unroll
    for (int i = 0; i < 4; i++) {
        xk[i] = g_xk[it * 4 + i];
        amp4[i] = g_amp[it * 4 + i];
    }

    float2 v[16];
#pragma unroll
    for (int i = 0; i < 16; i++) v[i] = make_float2(0.f, 0.f);
    v[0].x = 1.f;

#pragma unroll
    for (int i = 0; i < 4; i++) {
        float s, c;
        __sincosf(0.5f * xk[i], &s, &c);
        vRX(v, i, c, s);
    }
#pragma unroll
    for (int i = 0; i < 4; i++) vGEN(v, i, g_fused[20 + i]);
#pragma unroll
    for (int i = 0; i < 4; i++) {
        float2 t = g_cs[32 + i];
        vCRX(v, i, (i + 1) & 3, t.x, t.y);
    }
#pragma unroll
    for (int i = 0; i < 4; i++) {
        float2 t = g_cs[36 + i];
        vIXX(v, i, (i + 1) & 3, t.x, t.y);
    }
#pragma unroll
    for (int i = 0; i < 4; i++) vGEN(v, i, g_fused[24 + i]);
#pragma unroll
    for (int i = 0; i < 4; i++) {
        float ang = tanhf(amp4[i]) * __ldg(&score_gates[i]);
        float s, c;
        __sincosf(0.5f * ang, &s, &c);
        vRX(v, i, c, s);
    }
#pragma unroll
    for (int i = 0; i < 4; i++) vCNOT(v, i, (i + 1) & 3);

    float zres[4], xres[4];
#pragma unroll
    for (int w = 0; w < 4; w++) {
        float z = 0.f, x = 0.f;
#pragma unroll
        for (int i = 0; i < 16; i++) {
            float n = v[i].x * v[i].x + v[i].y * v[i].y;
            z += ((i >> w) & 1) ? -n : n;
            x += v[i].x * v[i ^ (1 << w)].x + v[i].y * v[i ^ (1 << w)].y;
        }
        zres[w] = z;
        xres[w] = x;
    }
    float4* o0 = (float4*)(out + (long)it * 8);
    o0[0] = make_float4(zres[0], zres[1], zres[2], zres[3]);
    o0[1] = make_float4(xres[0], xres[1], xres[2], xres[3]);
}

// ---------------------------------------------------------------------------

extern "C" void kernel_launch(void* const* d_in, const int* in_sizes, int n_in,
                              void* d_out, int out_size) {
    const float* x_text  = (const float*)d_in[0];
    const float* x_image = (const float*)d_in[1];
    const float* W_text  = (const float*)d_in[2];
    const float* b_text  = (const float*)d_in[3];
    const float* W_image = (const float*)d_in[4];
    const float* b_image = (const float*)d_in[5];
    const float* q_rot   = (const float*)d_in[6];
    const float* q_crx   = (const float*)d_in[7];
    const float* k_rot   = (const float*)d_in[8];
    const float* k_crx   = (const float*)d_in[9];
    const float* v_rot   = (const float*)d_in[10];
    const float* v_crx   = (const float*)d_in[11];
    const float* c_rot   = (const float*)d_in[12];
    const float* c_crx   = (const float*)d_in[13];
    const float* c_crx2  = (const float*)d_in[14];
    const float* gates   = (const float*)d_in[15];

    int IN = in_sizes[2] / 4;   // W_text is [4, IN]
    int B  = in_sizes[0] / IN;  // x_text is [B, IN]

    setup_kernel<<<1, 128>>>(q_rot, q_crx, k_rot, k_crx, v_rot, v_crx,
                             c_rot, c_crx, c_crx2);

    int threads = 256;
    int blocks = (B * 32 + threads - 1) / threads;
    score_kernel<<<blocks, threads>>>(x_text, x_image, W_text, b_text,
                                      W_image, b_image, B, IN);

    value_kernel<<<(B + 63) / 64, 64>>>(gates, (float*)d_out, B);
}

// round 3
// speedup vs baseline: 1.4163x; 1.1380x over previous
#include <cuda_runtime.h>

#define FULL 0xffffffffu

// ---------------------------------------------------------------------------
// Layout: half-warp (16 lanes) per batch item, 2 items per warp.
// 8-qubit state: 256 amps = 16 lanes x 16 local amps.
// Global amp index = (lg << 4) | j ; wire w<4 -> bit w of j (local),
// wire w>=4 -> bit (w-4) of lg (lane).
// ---------------------------------------------------------------------------

__device__ __forceinline__ float2 shfl2(float2 v, int m) {
    v.x = __shfl_xor_sync(FULL, v.x, m);
    v.y = __shfl_xor_sync(FULL, v.y, m);
    return v;
}

__device__ __forceinline__ float hred(float v) {  // sum over 16-lane group
#pragma unroll
    for (int o = 8; o; o >>= 1) v += __shfl_xor_sync(FULL, v, o);
    return v;
}

// a_new = c*a + (-i s)*o
__device__ __forceinline__ float2 rxmix(float2 a, float2 o, float c, float s) {
    return make_float2(c * a.x + s * o.y, c * a.y - s * o.x);
}

// ---- RX on wire w (no control) ----
__device__ __forceinline__ void gRX(float2* a, int lg, int w, float c, float s) {
    if (w < 4) {
        const int m = 1 << w;
#pragma unroll
        for (int j = 0; j < 16; j++)
            if (!(j & m)) {
                int j2 = j | m;
                float2 x = a[j], p = a[j2];
                a[j] = rxmix(x, p, c, s);
                a[j2] = rxmix(p, x, c, s);
            }
    } else {
        const int ml = 1 << (w - 4);
#pragma unroll
        for (int j = 0; j < 16; j++) {
            float2 t = shfl2(a[j], ml);
            a[j] = rxmix(a[j], t, c, s);
        }
    }
}

// ---- general fused 1-qubit unitary [[u00,u01],[-conj(u01),conj(u00)]] ----
// u = (u00.x, u00.y, u01.x, u01.y)
__device__ __forceinline__ void gGEN(float2* a, int lg, int w, float4 u) {
    if (w < 4) {
        const int m = 1 << w;
#pragma unroll
        for (int j = 0; j < 16; j++)
            if (!(j & m)) {
                int j2 = j | m;
                float2 x = a[j], p = a[j2];
                a[j] = make_float2(u.x * x.x - u.y * x.y + u.z * p.x - u.w * p.y,
                                   u.x * x.y + u.y * x.x + u.z * p.y + u.w * p.x);
                a[j2] = make_float2(u.x * p.x + u.y * p.y - u.z * x.x - u.w * x.y,
                                    u.x * p.y - u.y * p.x - u.z * x.y + u.w * x.x);
            }
    } else {
        const int ml = 1 << (w - 4);
        const int b = (lg >> (w - 4)) & 1;
        const float cx = u.x, cy = b ? -u.y : u.y;
        const float dx = b ? -u.z : u.z, dy = u.w;
#pragma unroll
        for (int j = 0; j < 16; j++) {
            float2 t = shfl2(a[j], ml);
            float2 x = a[j];
            a[j] = make_float2(cx * x.x - cy * x.y + dx * t.x - dy * t.y,
                               cx * x.y + cy * x.x + dx * t.y + dy * t.x);
        }
    }
}

// ---- CRX(wc -> wt) ----
__device__ __forceinline__ void gCRX(float2* a, int lg, int wc, int wt, float c, float s) {
    if (wc < 4 && wt < 4) {
        const int m = 1 << wt;
#pragma unroll
        for (int j = 0; j < 16; j++)
            if (((j >> wc) & 1) && !(j & m)) {
                int j2 = j | m;
                float2 x = a[j], p = a[j2];
                a[j] = rxmix(x, p, c, s);
                a[j2] = rxmix(p, x, c, s);
            }
    } else if (wc < 4) {  // local ctrl, lane target: only active j need gather
        const int ml = 1 << (wt - 4);
#pragma unroll
        for (int j = 0; j < 16; j++)
            if ((j >> wc) & 1) {
                float2 t = shfl2(a[j], ml);
                a[j] = rxmix(a[j], t, c, s);
            }
    } else if (wt < 4) {  // lane ctrl, local target: no shuffles
        const int ctrl = (lg >> (wc - 4)) & 1;
        const int m = 1 << wt;
        if (ctrl) {
#pragma unroll
            for (int j = 0; j < 16; j++)
                if (!(j & m)) {
                    int j2 = j | m;
                    float2 x = a[j], p = a[j2];
                    a[j] = rxmix(x, p, c, s);
                    a[j2] = rxmix(p, x, c, s);
                }
        }
    } else {  // lane ctrl, lane target
        const int ml = 1 << (wt - 4);
        const int ctrl = (lg >> (wc - 4)) & 1;
#pragma unroll
        for (int j = 0; j < 16; j++) {
            float2 t = shfl2(a[j], ml);
            if (ctrl) a[j] = rxmix(a[j], t, c, s);
        }
    }
}

// ---- IsingXX on (w1, w2): both local or both lane by construction ----
__device__ __forceinline__ void gIXX(float2* a, int lg, int w1, int w2, float c, float s) {
    if (w1 < 4 && w2 < 4) {
        const int m = (1 << w1) | (1 << w2);
        const int hb = (m >= 8) ? 8 : ((m >= 4) ? 4 : 2);
#pragma unroll
        for (int j = 0; j < 16; j++)
            if (!(j & hb)) {
                int j2 = j ^ m;
                float2 x = a[j], p = a[j2];
                a[j] = rxmix(x, p, c, s);
                a[j2] = rxmix(p, x, c, s);
            }
    } else {
        const int ml = (1 << (w1 - 4)) | (1 << (w2 - 4));
#pragma unroll
        for (int j = 0; j < 16; j++) {
            float2 t = shfl2(a[j], ml);
            a[j] = rxmix(a[j], t, c, s);
        }
    }
}

// ---- CNOT(wc -> wt): only mixed local/lane cases occur ----
__device__ __forceinline__ void gCNOT(float2* a, int lg, int wc, int wt) {
    if (wc < 4) {  // local ctrl, lane target
        const int ml = 1 << (wt - 4);
#pragma unroll
        for (int j = 0; j < 16; j++)
            if ((j >> wc) & 1) {
                float2 t = shfl2(a[j], ml);
                a[j] = t;
            }
    } else {  // lane ctrl, local target
        const int ctrl = (lg >> (wc - 4)) & 1;
        const int m = 1 << wt;
        if (ctrl) {
#pragma unroll
            for (int j = 0; j < 16; j++)
                if (!(j & m)) {
                    int j2 = j | m;
                    float2 t = a[j];
                    a[j] = a[j2];
                    a[j2] = t;
                }
        }
    }
}

// ---------------------------------------------------------------------------

__global__ void __launch_bounds__(64)
qa_fused(const float* __restrict__ x_text, const float* __restrict__ x_image,
         const float* __restrict__ W_text, const float* __restrict__ b_text,
         const float* __restrict__ W_image, const float* __restrict__ b_image,
         const float* __restrict__ qr, const float* __restrict__ qc,
         const float* __restrict__ kr, const float* __restrict__ kc,
         const float* __restrict__ vr, const float* __restrict__ vc,
         const float* __restrict__ cr, const float* __restrict__ cc,
         const float* __restrict__ cc2, const float* __restrict__ gates,
         float* __restrict__ out, int B, int IN) {
    // fused triples: [0..3] q L1, [4..7] q L2, [8..11] k L1, [12..15] k L2,
    //                [16..19] cross, [20..23] v L1, [24..27] v L2
    __shared__ float4 sf[28];
    // cs: [0..7] q_crx, [8..15] k_crx, [16..23] c_crx, [24..31] c_crx2, [32..39] v_crx
    __shared__ float2 scs[40];

    for (int t = threadIdx.x; t < 68; t += blockDim.x) {
        if (t < 28) {
            int grp = t >> 2, i = t & 3;
            float a = 0.f, b = 0.f, c = 0.f;
            switch (grp) {
                case 0: a = qr[3 * i];      b = qr[3 * i + 1];      c = qr[3 * i + 2];      break;
                case 1: a = qr[12 + 3 * i]; b = qr[12 + 3 * i + 1]; c = qr[12 + 3 * i + 2]; break;
                case 2: a = kr[3 * i];      b = kr[3 * i + 1];      c = kr[3 * i + 2];      break;
                case 3: a = kr[12 + 3 * i]; b = kr[12 + 3 * i + 1]; c = kr[12 + 3 * i + 2]; break;
                case 4: a = cr[3 * i];      b = cr[3 * i + 1];      c = cr[3 * i + 2];      break;
                case 5: a = vr[3 * i];      b = vr[3 * i + 1];      c = vr[3 * i + 2];      break;
                case 6: a = vr[12 + 3 * i]; b = vr[12 + 3 * i + 1]; c = vr[12 + 3 * i + 2]; break;
            }
            float cb = cosf(0.5f * b), sb = sinf(0.5f * b);
            float sum = 0.5f * (a + c), dif = 0.5f * (a - c);
            sf[t] = make_float4(cb * cosf(sum), -cb * sinf(sum),
                                sb * sinf(dif), -sb * cosf(dif));
        } else {
            int u = t - 28;
            float p;
            if (u < 8) p = qc[u];
            else if (u < 16) p = kc[u - 8];
            else if (u < 24) p = cc[u - 16];
            else if (u < 32) p = cc2[u - 24];
            else p = vc[u - 32];
            float s, c;
            sincosf(0.5f * p, &s, &c);
            scs[u] = make_float2(c, s);
        }
    }
    __syncthreads();

    const int lane = threadIdx.x & 31;
    const int half = lane >> 4;
    const int lg = lane & 15;
    const int gw = (int)((blockIdx.x * blockDim.x + threadIdx.x) >> 5);
    const int item = gw * 2 + half;
    const int itc = item < B ? item : (B - 1);  // clamp for safe loads

    // ---- projections ----
    float xq[4], xk[4];
    {
        const float* xt = x_text + (long)itc * IN;
        const float* xi = x_image + (long)itc * IN;
#pragma unroll
        for (int r = 0; r < 4; r++) {
            float pq = 0.f, pk = 0.f;
            for (int k = lg; k < IN; k += 16) {
                pq += xt[k] * __ldg(&W_text[r * IN + k]);
                pk += xi[k] * __ldg(&W_image[r * IN + k]);
            }
            xq[r] = hred(pq) + __ldg(&b_text[r]);
            xk[r] = hred(pk) + __ldg(&b_image[r]);
        }
    }

    // ---- score circuit ----
    float2 a[16];
#pragma unroll
    for (int j = 0; j < 16; j++) a[j] = make_float2(0.f, 0.f);
    if (lg == 0) a[0].x = 1.f;

#pragma unroll
    for (int i = 0; i < 4; i++) {
        float s, c;
        __sincosf(0.5f * xq[i], &s, &c);
        gRX(a, lg, i, c, s);
    }
    // q two-ring (all local)
#pragma unroll
    for (int i = 0; i < 4; i++) gGEN(a, lg, i, sf[i]);
#pragma unroll
    for (int i = 0; i < 4; i++) gCRX(a, lg, i, (i + 1) & 3, scs[i].x, scs[i].y);
#pragma unroll
    for (int i = 0; i < 4; i++) gIXX(a, lg, i, (i + 1) & 3, scs[4 + i].x, scs[4 + i].y);
#pragma unroll
    for (int i = 0; i < 4; i++) gGEN(a, lg, i, sf[4 + i]);

#pragma unroll
    for (int i = 0; i < 4; i++) {
        float s, c;
        __sincosf(0.5f * xk[i], &s, &c);
        gRX(a, lg, 4 + i, c, s);
    }
    // k two-ring (all lane)
#pragma unroll
    for (int i = 0; i < 4; i++) gGEN(a, lg, 4 + i, sf[8 + i]);
#pragma unroll
    for (int i = 0; i < 4; i++) gCRX(a, lg, 4 + i, 4 + ((i + 1) & 3), scs[8 + i].x, scs[8 + i].y);
#pragma unroll
    for (int i = 0; i < 4; i++) gIXX(a, lg, 4 + i, 4 + ((i + 1) & 3), scs[12 + i].x, scs[12 + i].y);
#pragma unroll
    for (int i = 0; i < 4; i++) gGEN(a, lg, 4 + i, sf[12 + i]);

    // cross entanglers
#pragma unroll
    for (int i = 0; i < 4; i++) {
        gCRX(a, lg, i, 4 + i, scs[16 + i].x, scs[16 + i].y);
        gCRX(a, lg, 4 + i, i, scs[20 + i].x, scs[20 + i].y);
    }
#pragma unroll
    for (int i = 0; i < 4; i++) gCRX(a, lg, i, ((i + 1) & 3) + 4, scs[24 + i].x, scs[24 + i].y);
#pragma unroll
    for (int i = 0; i < 4; i++) gCRX(a, lg, 4 + i, (i + 1) & 3, scs[28 + i].x, scs[28 + i].y);
#pragma unroll
    for (int i = 0; i < 4; i++) {
        gCNOT(a, lg, i, 4 + i);
        gCNOT(a, lg, 4 + i, i);
    }
    // final rot layer (wires 0..3, local)
#pragma unroll
    for (int i = 0; i < 4; i++) gGEN(a, lg, i, sf[16 + i]);

    // measurements -> amp (wires 0..3 are local: no shuffles in gathers)
    float amp4[4];
#pragma unroll
    for (int w = 0; w < 4; w++) {
        const int m = 1 << w;
        float z = 0.f, x = 0.f;
#pragma unroll
        for (int j = 0; j < 16; j++) {
            float n = a[j].x * a[j].x + a[j].y * a[j].y;
            z += (j & m) ? -n : n;
            float2 o = a[j ^ m];
            x += a[j].x * o.x + a[j].y * o.y;
        }
        z = hred(z);
        x = hred(x);
        amp4[w] = sqrtf(z * z + x * x);
    }

    // ---- value circuit: 16 amps distributed 1/lane across the 16-lane group ----
    float2 v = make_float2((lg == 0) ? 1.f : 0.f, 0.f);

#pragma unroll
    for (int i = 0; i < 4; i++) {
        float s, c;
        __sincosf(0.5f * xk[i], &s, &c);
        float2 t = shfl2(v, 1 << i);
        v = rxmix(v, t, c, s);
    }
#pragma unroll
    for (int i = 0; i < 4; i++) {  // v rot layer 1 (fused)
        float4 u = sf[20 + i];
        int b = (lg >> i) & 1;
        float cx = u.x, cy = b ? -u.y : u.y;
        float dx = b ? -u.z : u.z, dy = u.w;
        float2 t = shfl2(v, 1 << i);
        v = make_float2(cx * v.x - cy * v.y + dx * t.x - dy * t.y,
                        cx * v.y + cy * v.x + dx * t.y + dy * t.x);
    }
#pragma unroll
    for (int i = 0; i < 4; i++) {  // CRX ring
        float2 cs = scs[32 + i];
        float2 t = shfl2(v, 1 << ((i + 1) & 3));
        if ((lg >> i) & 1) v = rxmix(v, t, cs.x, cs.y);
    }
#pragma unroll
    for (int i = 0; i < 4; i++) {  // IsingXX ring
        float2 cs = scs[36 + i];
        float2 t = shfl2(v, (1 << i) | (1 << ((i + 1) & 3)));
        v = rxmix(v, t, cs.x, cs.y);
    }
#pragma unroll
    for (int i = 0; i < 4; i++) {  // v rot layer 2 (fused)
        float4 u = sf[24 + i];
        int b = (lg >> i) & 1;
        float cx = u.x, cy = b ? -u.y : u.y;
        float dx = b ? -u.z : u.z, dy = u.w;
        float2 t = shfl2(v, 1 << i);
        v = make_float2(cx * v.x - cy * v.y + dx * t.x - dy * t.y,
                        cx * v.y + cy * v.x + dx * t.y + dy * t.x);
    }
#pragma unroll
    for (int i = 0; i < 4; i++) {  // amplitude-modulated RX
        float ang = tanhf(amp4[i]) * __ldg(&gates[i]);
        float s, c;
        __sincosf(0.5f * ang, &s, &c);
        float2 t = shfl2(v, 1 << i);
        v = rxmix(v, t, c, s);
    }
#pragma unroll
    for (int i = 0; i < 4; i++) {  // CNOT ring
        float2 t = shfl2(v, 1 << ((i + 1) & 3));
        if ((lg >> i) & 1) v = t;
    }

    // measure + store
    float zres[4], xres[4];
#pragma unroll
    for (int w = 0; w < 4; w++) {
        float n = v.x * v.x + v.y * v.y;
        zres[w] = hred(((lg >> w) & 1) ? -n : n);
        float2 t = shfl2(v, 1 << w);
        xres[w] = hred(v.x * t.x + v.y * t.y);
    }
    if (lg == 0 && item < B) {
        float4* o0 = (float4*)(out + (long)item * 8);
        o0[0] = make_float4(zres[0], zres[1], zres[2], zres[3]);
        o0[1] = make_float4(xres[0], xres[1], xres[2], xres[3]);
    }
}

// ---------------------------------------------------------------------------

extern "C" void kernel_launch(void* const* d_in, const int* in_sizes, int n_in,
                              void* d_out, int out_size) {
    const float* x_text  = (const float*)d_in[0];
    const float* x_image = (const float*)d_in[1];
    const float* W_text  = (const float*)d_in[2];
    const float* b_text  = (const float*)d_in[3];
    const float* W_image = (const float*)d_in[4];
    const float* b_image = (const float*)d_in[5];
    const float* q_rot   = (const float*)d_in[6];
    const float* q_crx   = (const float*)d_in[7];
    const float* k_rot   = (const float*)d_in[8];
    const float* k_crx   = (const float*)d_in[9];
    const float* v_rot   = (const float*)d_in[10];
    const float* v_crx   = (const float*)d_in[11];
    const float* c_rot   = (const float*)d_in[12];
    const float* c_crx   = (const float*)d_in[13];
    const float* c_crx2  = (const float*)d_in[14];
    const float* gates   = (const float*)d_in[15];

    int IN = in_sizes[2] / 4;   // W_text is [4, IN]
    int B  = in_sizes[0] / IN;  // x_text is [B, IN]

    int nwarps = (B + 1) / 2;             // 2 items per warp
    int threads = 64;                      // small blocks -> good wave balance
    int blocks = (nwarps * 32 + threads - 1) / threads;
    qa_fused<<<blocks, threads>>>(x_text, x_image, W_text, b_text, W_image, b_image,
                                  q_rot, q_crx, k_rot, k_crx, v_rot, v_crx,
                                  c_rot, c_crx, c_crx2, gates,
                                  (float*)d_out, B, IN);
}

// round 4
// speedup vs baseline: 2.4725x; 1.7457x over previous
#include <cuda_runtime.h>

#define FULL 0xffffffffu

// ---------------------------------------------------------------------------
// Layout: half-warp (16 lanes) per batch item, 2 items per warp.
// Full 8-qubit state (only for the cross section): 256 amps = 16 lanes x 16
// local amps. Global amp index = (lg << 4) | j ; wire w<4 -> bit w of j,
// wire w>=4 -> bit (w-4) of lg.
// Before the cross section the state is a tensor product, so the q- and
// k-registers are simulated as distributed 16-amp states (1 amp per lane).
// ---------------------------------------------------------------------------

__device__ __forceinline__ float2 shfl2x(float2 v, int m) {
    v.x = __shfl_xor_sync(FULL, v.x, m);
    v.y = __shfl_xor_sync(FULL, v.y, m);
    return v;
}
__device__ __forceinline__ float2 shfl2i(float2 v, int src) {  // within 16-group
    v.x = __shfl_sync(FULL, v.x, src, 16);
    v.y = __shfl_sync(FULL, v.y, src, 16);
    return v;
}
__device__ __forceinline__ float hred(float v) {  // sum over 16-lane group
#pragma unroll
    for (int o = 8; o; o >>= 1) v += __shfl_xor_sync(FULL, v, o);
    return v;
}

// a_new = c*a + (-i s)*o
__device__ __forceinline__ float2 rxmix(float2 a, float2 o, float c, float s) {
    return make_float2(c * a.x + s * o.y, c * a.y - s * o.x);
}

// general unitary [[u00,u01],[-conj(u01),conj(u00)]], u=(u00.x,u00.y,u01.x,u01.y)
// applied to own amp x with partner t, own wire-bit b
__device__ __forceinline__ float2 genmix(float2 x, float2 t, float4 u, int b) {
    float cx = u.x, cy = b ? -u.y : u.y;
    float dx = b ? -u.z : u.z, dy = u.w;
    return make_float2(cx * x.x - cy * x.y + dx * t.x - dy * t.y,
                       cx * x.y + cy * x.x + dx * t.y + dy * t.x);
}

// Distributed 16-amp register (1 amp/lane within 16-group):
// |0000> -> RX(xin_i) embeddings fused into rot layer L1 -> CRX ring ->
// IsingXX ring -> rot layer L2.  Wire i <-> bit i of lg.
__device__ __forceinline__ float2 ring16(int lg, const float* xin,
                                         const float4* L1, const float4* L2,
                                         const float2* cs) {
    float2 v = make_float2(lg == 0 ? 1.f : 0.f, 0.f);
#pragma unroll
    for (int i = 0; i < 4; i++) {
        float s, c;
        __sincosf(0.5f * xin[i], &s, &c);
        float4 g = L1[i];
        // U = GEN @ RX(xin): u00 = rxmix(g00,g01), u01 = rxmix(g01,g00)
        float2 g00 = make_float2(g.x, g.y), g01 = make_float2(g.z, g.w);
        float2 u00 = rxmix(g00, g01, c, s);
        float2 u01 = rxmix(g01, g00, c, s);
        float4 u = make_float4(u00.x, u00.y, u01.x, u01.y);
        float2 t = shfl2x(v, 1 << i);
        v = genmix(v, t, u, (lg >> i) & 1);
    }
#pragma unroll
    for (int i = 0; i < 4; i++) {  // CRX ring
        float2 t = shfl2x(v, 1 << ((i + 1) & 3));
        if ((lg >> i) & 1) v = rxmix(v, t, cs[i].x, cs[i].y);
    }
#pragma unroll
    for (int i = 0; i < 4; i++) {  // IsingXX ring
        float2 t = shfl2x(v, (1 << i) | (1 << ((i + 1) & 3)));
        v = rxmix(v, t, cs[4 + i].x, cs[4 + i].y);
    }
#pragma unroll
    for (int i = 0; i < 4; i++) {  // rot layer L2
        float2 t = shfl2x(v, 1 << i);
        v = genmix(v, t, L2[i], (lg >> i) & 1);
    }
    return v;
}

// ---- full-state gates (cross section only) ----

// CRX local ctrl (wc<4), lane target (wt>=4)
__device__ __forceinline__ void fCRX_lt(float2* a, int wc, int wt, float c, float s) {
    const int ml = 1 << (wt - 4);
#pragma unroll
    for (int j = 0; j < 16; j++)
        if ((j >> wc) & 1) {  // j is compile-time uniform: no divergence
            float2 t = shfl2x(a[j], ml);
            a[j] = rxmix(a[j], t, c, s);
        }
}

// CRX lane ctrl (wc>=4), local target (wt<4): no shuffles
__device__ __forceinline__ void fCRX_ll(float2* a, int lg, int wc, int wt, float c, float s) {
    if ((lg >> (wc - 4)) & 1) {
        const int m = 1 << wt;
#pragma unroll
        for (int j = 0; j < 16; j++)
            if (!(j & m)) {
                int j2 = j | m;
                float2 x = a[j], p = a[j2];
                a[j] = rxmix(x, p, c, s);
                a[j2] = rxmix(p, x, c, s);
            }
    }
}

__device__ __forceinline__ void fCNOT_lt(float2* a, int wc, int wt) {
    const int ml = 1 << (wt - 4);
#pragma unroll
    for (int j = 0; j < 16; j++)
        if ((j >> wc) & 1) {
            float2 t = shfl2x(a[j], ml);
            a[j] = t;
        }
}

__device__ __forceinline__ void fCNOT_ll(float2* a, int lg, int wc, int wt) {
    if ((lg >> (wc - 4)) & 1) {
        const int m = 1 << wt;
#pragma unroll
        for (int j = 0; j < 16; j++)
            if (!(j & m)) {
                int j2 = j | m;
                float2 t = a[j];
                a[j] = a[j2];
                a[j2] = t;
            }
    }
}

// general 1-qubit unitary on local wire w<4
__device__ __forceinline__ void fGEN_loc(float2* a, int w, float4 u) {
    const int m = 1 << w;
#pragma unroll
    for (int j = 0; j < 16; j++)
        if (!(j & m)) {
            int j2 = j | m;
            float2 x = a[j], p = a[j2];
            a[j] = make_float2(u.x * x.x - u.y * x.y + u.z * p.x - u.w * p.y,
                               u.x * x.y + u.y * x.x + u.z * p.y + u.w * p.x);
            a[j2] = make_float2(u.x * p.x + u.y * p.y - u.z * x.x - u.w * x.y,
                                u.x * p.y - u.y * p.x - u.z * x.y + u.w * x.x);
        }
}

// ---------------------------------------------------------------------------

__global__ void __launch_bounds__(64)
qa_fused(const float* __restrict__ x_text, const float* __restrict__ x_image,
         const float* __restrict__ W_text, const float* __restrict__ b_text,
         const float* __restrict__ W_image, const float* __restrict__ b_image,
         const float* __restrict__ qr, const float* __restrict__ qc,
         const float* __restrict__ kr, const float* __restrict__ kc,
         const float* __restrict__ vr, const float* __restrict__ vc,
         const float* __restrict__ cr, const float* __restrict__ cc,
         const float* __restrict__ cc2, const float* __restrict__ gates,
         float* __restrict__ out, int B, int IN) {
    // fused triples: [0..3] q L1, [4..7] q L2, [8..11] k L1, [12..15] k L2,
    //                [16..19] cross final, [20..23] v L1, [24..27] v L2
    __shared__ float4 sf[28];
    // cs: [0..7] q_crx, [8..15] k_crx, [16..23] c_crx, [24..31] c_crx2, [32..39] v_crx
    __shared__ float2 scs[40];

    for (int t = threadIdx.x; t < 68; t += blockDim.x) {
        if (t < 28) {
            int grp = t >> 2, i = t & 3;
            float a = 0.f, b = 0.f, c = 0.f;
            switch (grp) {
                case 0: a = qr[3 * i];      b = qr[3 * i + 1];      c = qr[3 * i + 2];      break;
                case 1: a = qr[12 + 3 * i]; b = qr[12 + 3 * i + 1]; c = qr[12 + 3 * i + 2]; break;
                case 2: a = kr[3 * i];      b = kr[3 * i + 1];      c = kr[3 * i + 2];      break;
                case 3: a = kr[12 + 3 * i]; b = kr[12 + 3 * i + 1]; c = kr[12 + 3 * i + 2]; break;
                case 4: a = cr[3 * i];      b = cr[3 * i + 1];      c = cr[3 * i + 2];      break;
                case 5: a = vr[3 * i];      b = vr[3 * i + 1];      c = vr[3 * i + 2];      break;
                case 6: a = vr[12 + 3 * i]; b = vr[12 + 3 * i + 1]; c = vr[12 + 3 * i + 2]; break;
            }
            float cb = cosf(0.5f * b), sb = sinf(0.5f * b);
            float sum = 0.5f * (a + c), dif = 0.5f * (a - c);
            sf[t] = make_float4(cb * cosf(sum), -cb * sinf(sum),
                                sb * sinf(dif), -sb * cosf(dif));
        } else {
            int u = t - 28;
            float p;
            if (u < 8) p = qc[u];
            else if (u < 16) p = kc[u - 8];
            else if (u < 24) p = cc[u - 16];
            else if (u < 32) p = cc2[u - 24];
            else p = vc[u - 32];
            float s, c;
            sincosf(0.5f * p, &s, &c);
            scs[u] = make_float2(c, s);
        }
    }
    __syncthreads();

    const int lane = threadIdx.x & 31;
    const int half = lane >> 4;
    const int lg = lane & 15;
    const int gw = (int)((blockIdx.x * blockDim.x + threadIdx.x) >> 5);
    const int item = gw * 2 + half;
    const int itc = item < B ? item : (B - 1);

    // ---- projections ----
    float xq[4], xk[4];
    {
        const float* xt = x_text + (long)itc * IN;
        const float* xi = x_image + (long)itc * IN;
#pragma unroll
        for (int r = 0; r < 4; r++) {
            float pq = 0.f, pk = 0.f;
            for (int k = lg; k < IN; k += 16) {
                pq += xt[k] * __ldg(&W_text[r * IN + k]);
                pk += xi[k] * __ldg(&W_image[r * IN + k]);
            }
            xq[r] = hred(pq) + __ldg(&b_text[r]);
            xk[r] = hred(pk) + __ldg(&b_image[r]);
        }
    }

    // ---- product-state phase: psi_q and psi_k as distributed 16-amp states ----
    float2 q  = ring16(lg, xq, sf + 0,  sf + 4,  scs + 0);
    float2 kk = ring16(lg, xk, sf + 8,  sf + 12, scs + 8);

    // ---- assemble full 256-amp state: a[j] = psi_q[j] * psi_k[lg] ----
    float2 a[16];
#pragma unroll
    for (int j = 0; j < 16; j++) {
        float2 qj = shfl2i(q, j);
        a[j] = make_float2(qj.x * kk.x - qj.y * kk.y,
                           qj.x * kk.y + qj.y * kk.x);
    }

    // ---- cross entanglers ----
#pragma unroll
    for (int i = 0; i < 4; i++) {
        fCRX_lt(a, i, 4 + i, scs[16 + i].x, scs[16 + i].y);
        fCRX_ll(a, lg, 4 + i, i, scs[20 + i].x, scs[20 + i].y);
    }
#pragma unroll
    for (int i = 0; i < 4; i++)
        fCRX_lt(a, i, ((i + 1) & 3) + 4, scs[24 + i].x, scs[24 + i].y);
#pragma unroll
    for (int i = 0; i < 4; i++)
        fCRX_ll(a, lg, 4 + i, (i + 1) & 3, scs[28 + i].x, scs[28 + i].y);
#pragma unroll
    for (int i = 0; i < 4; i++) {
        fCNOT_lt(a, i, 4 + i);
        fCNOT_ll(a, lg, 4 + i, i);
    }
    // final rot layer (wires 0..3, local)
#pragma unroll
    for (int i = 0; i < 4; i++) fGEN_loc(a, i, sf[16 + i]);

    // ---- measurements -> amp (wires 0..3 local: register gathers only) ----
    float amp4[4];
#pragma unroll
    for (int w = 0; w < 4; w++) {
        const int m = 1 << w;
        float z = 0.f, x = 0.f;
#pragma unroll
        for (int j = 0; j < 16; j++) {
            float n = a[j].x * a[j].x + a[j].y * a[j].y;
            z += (j & m) ? -n : n;
            float2 o = a[j ^ m];
            x += a[j].x * o.x + a[j].y * o.y;
        }
        z = hred(z);
        x = hred(x);
        amp4[w] = sqrtf(z * z + x * x);
    }

    // ---- value circuit: distributed 16-amp state ----
    float2 v = ring16(lg, xk, sf + 20, sf + 24, scs + 32);
#pragma unroll
    for (int i = 0; i < 4; i++) {  // amplitude-modulated RX
        float ang = tanhf(amp4[i]) * __ldg(&gates[i]);
        float s, c;
        __sincosf(0.5f * ang, &s, &c);
        float2 t = shfl2x(v, 1 << i);
        v = rxmix(v, t, c, s);
    }
#pragma unroll
    for (int i = 0; i < 4; i++) {  // CNOT ring
        float2 t = shfl2x(v, 1 << ((i + 1) & 3));
        if ((lg >> i) & 1) v = t;
    }

    // ---- measure + store ----
    float zres[4], xres[4];
#pragma unroll
    for (int w = 0; w < 4; w++) {
        float n = v.x * v.x + v.y * v.y;
        zres[w] = hred(((lg >> w) & 1) ? -n : n);
        float2 t = shfl2x(v, 1 << w);
        xres[w] = hred(v.x * t.x + v.y * t.y);
    }
    if (lg == 0 && item < B) {
        float4* o0 = (float4*)(out + (long)item * 8);
        o0[0] = make_float4(zres[0], zres[1], zres[2], zres[3]);
        o0[1] = make_float4(xres[0], xres[1], xres[2], xres[3]);
    }
}

// ---------------------------------------------------------------------------

extern "C" void kernel_launch(void* const* d_in, const int* in_sizes, int n_in,
                              void* d_out, int out_size) {
    const float* x_text  = (const float*)d_in[0];
    const float* x_image = (const float*)d_in[1];
    const float* W_text  = (const float*)d_in[2];
    const float* b_text  = (const float*)d_in[3];
    const float* W_image = (const float*)d_in[4];
    const float* b_image = (const float*)d_in[5];
    const float* q_rot   = (const float*)d_in[6];
    const float* q_crx   = (const float*)d_in[7];
    const float* k_rot   = (const float*)d_in[8];
    const float* k_crx   = (const float*)d_in[9];
    const float* v_rot   = (const float*)d_in[10];
    const float* v_crx   = (const float*)d_in[11];
    const float* c_rot   = (const float*)d_in[12];
    const float* c_crx   = (const float*)d_in[13];
    const float* c_crx2  = (const float*)d_in[14];
    const float* gates   = (const float*)d_in[15];

    int IN = in_sizes[2] / 4;   // W_text is [4, IN]
    int B  = in_sizes[0] / IN;  // x_text is [B, IN]

    int nwarps = (B + 1) / 2;   // 2 items per warp
    int threads = 64;
    int blocks = (nwarps * 32 + threads - 1) / threads;
    qa_fused<<<blocks, threads>>>(x_text, x_image, W_text, b_text, W_image, b_image,
                                  q_rot, q_crx, k_rot, k_crx, v_rot, v_crx,
                                  c_rot, c_crx, c_crx2, gates,
                                  (float*)d_out, B, IN);
}